// round 2
// baseline (speedup 1.0000x reference)
#include <cuda_runtime.h>
#include <math.h>

#define NN 50000
#define NE 800000
#define NG 1024
#define DD 128
#define NL 3

typedef unsigned long long u64;

// -------- scratch (device globals: allocation-free) --------
__device__ float d_h[(size_t)NN * DD];        // node features
__device__ float d_zb[(size_t)NN * DD];       // z = (1+eps)h + agg
__device__ float d_tb[(size_t)NN * 2 * DD];   // MLP hidden
__device__ float d_vn[NG * DD];
__device__ float d_vnagg[NG * DD];
__device__ float d_vnt[NG * 2 * DD];
__device__ int   d_deg[NN];
__device__ int   d_off[NN];
__device__ int   d_cur[NN];
__device__ int   d_srcs[NE];
__device__ int   d_attrs[NE];

// -------- packed f32x2 helpers (Blackwell FFMA2 — ptxas never auto-fuses) ----
__device__ __forceinline__ u64 pack2(float lo, float hi) {
    u64 r; asm("mov.b64 %0, {%1, %2};" : "=l"(r) : "f"(lo), "f"(hi)); return r;
}
__device__ __forceinline__ u64 dup2(float v) {
    u64 r; asm("mov.b64 %0, {%1, %1};" : "=l"(r) : "f"(v)); return r;
}
__device__ __forceinline__ void ffma2(u64 &acc, u64 a, u64 b) {
    asm("fma.rn.f32x2 %0, %1, %2, %0;" : "+l"(acc) : "l"(a), "l"(b));
}
__device__ __forceinline__ float2 unpack2(u64 v) {
    float2 f; asm("mov.b64 {%0, %1}, %2;" : "=f"(f.x), "=f"(f.y) : "l"(v)); return f;
}

// ================= CSR build =================
__global__ void k_zero_deg() {
    int i = blockIdx.x * blockDim.x + threadIdx.x;
    if (i < NN) d_deg[i] = 0;
}

__global__ void k_hist(const int* __restrict__ ei) {
    int e = blockIdx.x * blockDim.x + threadIdx.x;
    if (e < NE) atomicAdd(&d_deg[ei[NE + e]], 1);
}

// single-block exclusive scan of d_deg -> d_off, d_cur
__global__ void k_scan() {
    __shared__ int wsum[32];
    __shared__ int s_carry;
    int tid = threadIdx.x;               // 1024 threads
    int lane = tid & 31, wid = tid >> 5;
    if (tid == 0) s_carry = 0;
    __syncthreads();
    for (int base = 0; base < NN; base += 1024) {
        int i = base + tid;
        int v = (i < NN) ? d_deg[i] : 0;
        int x = v;
        #pragma unroll
        for (int o = 1; o < 32; o <<= 1) {
            int y = __shfl_up_sync(0xffffffffu, x, o);
            if (lane >= o) x += y;
        }
        if (lane == 31) wsum[wid] = x;
        __syncthreads();
        if (wid == 0) {
            int s = wsum[lane];
            #pragma unroll
            for (int o = 1; o < 32; o <<= 1) {
                int y = __shfl_up_sync(0xffffffffu, s, o);
                if (lane >= o) s += y;
            }
            wsum[lane] = s;
        }
        __syncthreads();
        int warpExcl = (wid > 0) ? wsum[wid - 1] : 0;
        int excl = s_carry + warpExcl + (x - v);
        if (i < NN) { d_off[i] = excl; d_cur[i] = excl; }
        __syncthreads();
        if (tid == 0) s_carry += wsum[31];
        __syncthreads();
    }
}

__global__ void k_scatter(const int* __restrict__ ei, const int* __restrict__ ea) {
    int e = blockIdx.x * blockDim.x + threadIdx.x;
    if (e >= NE) return;
    int dst = ei[NE + e];
    int pos = atomicAdd(&d_cur[dst], 1);
    d_srcs[pos]  = ei[e];
    d_attrs[pos] = ea[3 * e] | (ea[3 * e + 1] << 8) | (ea[3 * e + 2] << 16);
}

// ================= encoders / vn =================
__global__ void k_atom(const int* __restrict__ x_atom,
                       const float* __restrict__ atom_emb,
                       const float* __restrict__ vn0) {
    int n = blockIdx.x;
    int d = threadIdx.x;    // 128
    const int* xr = x_atom + n * 9;
    float s = vn0[d];       // layer-0 vn broadcast fused (vn identical per graph)
    #pragma unroll
    for (int f = 0; f < 9; f++)
        s += atom_emb[(f * 100 + xr[f]) * DD + d];
    d_h[(size_t)n * DD + d] = s;
}

__global__ void k_vninit(const float* __restrict__ vn0) {
    d_vn[blockIdx.x * DD + threadIdx.x] = vn0[threadIdx.x];
}

// per-graph segment sum of h (batch is sorted) -> vnagg = sum + vn
__global__ void k_vnagg(const int* __restrict__ batch) {
    __shared__ int s_se[2];
    __shared__ float s_acc[DD];
    int g = blockIdx.x;
    if (threadIdx.x < 2) {
        int target = g + threadIdx.x;
        int lo = 0, hi = NN;
        while (lo < hi) {
            int mid = (lo + hi) >> 1;
            if (batch[mid] < target) lo = mid + 1; else hi = mid;
        }
        s_se[threadIdx.x] = lo;
    }
    __syncthreads();
    int start = s_se[0], end = s_se[1];
    int d = threadIdx.x & (DD - 1);
    int half = threadIdx.x >> 7;     // 256 threads -> 2 nodes in flight
    float acc = 0.f;
    for (int n = start + half; n < end; n += 2)
        acc += d_h[(size_t)n * DD + d];
    if (half == 0) s_acc[d] = acc;
    __syncthreads();
    if (half == 1)
        d_vnagg[g * DD + d] = (acc + s_acc[d]) + d_vn[g * DD + d];
}

// ================= per-node message aggregation (CSR gather) =================
// z[n] = (1+eps_l)*h[n] + sum_{edges into n} relu(h[src] + bond_emb)
__global__ void __launch_bounds__(256) k_aggregate(const float* __restrict__ bond_l,
                                                   const float* __restrict__ eps, int l) {
    __shared__ float tbl[3 * 10 * DD];   // 15KB bond tables for this layer
    for (int i = threadIdx.x; i < 3 * 10 * DD; i += 256) tbl[i] = bond_l[i];
    __syncthreads();
    int node = blockIdx.x * 8 + (threadIdx.x >> 5);
    if (node >= NN) return;
    int lane = threadIdx.x & 31;
    int d4 = lane * 4;
    int start = d_off[node];
    int deg   = d_deg[node];
    float4 acc = make_float4(0.f, 0.f, 0.f, 0.f);
    int j = 0;
    for (; j + 2 <= deg; j += 2) {   // 2 edges in flight (double the gather MLP)
        int s0 = d_srcs[start + j],     p0 = d_attrs[start + j];
        int s1 = d_srcs[start + j + 1], p1 = d_attrs[start + j + 1];
        float4 hv0 = *(const float4*)&d_h[(size_t)s0 * DD + d4];
        float4 hv1 = *(const float4*)&d_h[(size_t)s1 * DD + d4];
        float4 a0 = *(const float4*)&tbl[(p0 & 255) * DD + d4];
        float4 a1 = *(const float4*)&tbl[10 * DD + ((p0 >> 8) & 255) * DD + d4];
        float4 a2 = *(const float4*)&tbl[20 * DD + ((p0 >> 16) & 255) * DD + d4];
        float4 c0 = *(const float4*)&tbl[(p1 & 255) * DD + d4];
        float4 c1 = *(const float4*)&tbl[10 * DD + ((p1 >> 8) & 255) * DD + d4];
        float4 c2 = *(const float4*)&tbl[20 * DD + ((p1 >> 16) & 255) * DD + d4];
        acc.x += fmaxf(hv0.x + a0.x + a1.x + a2.x, 0.f) + fmaxf(hv1.x + c0.x + c1.x + c2.x, 0.f);
        acc.y += fmaxf(hv0.y + a0.y + a1.y + a2.y, 0.f) + fmaxf(hv1.y + c0.y + c1.y + c2.y, 0.f);
        acc.z += fmaxf(hv0.z + a0.z + a1.z + a2.z, 0.f) + fmaxf(hv1.z + c0.z + c1.z + c2.z, 0.f);
        acc.w += fmaxf(hv0.w + a0.w + a1.w + a2.w, 0.f) + fmaxf(hv1.w + c0.w + c1.w + c2.w, 0.f);
    }
    if (j < deg) {
        int src = d_srcs[start + j];
        int pa  = d_attrs[start + j];
        float4 hv = *(const float4*)&d_h[(size_t)src * DD + d4];
        float4 b0 = *(const float4*)&tbl[(pa & 255) * DD + d4];
        float4 b1 = *(const float4*)&tbl[10 * DD + ((pa >> 8) & 255) * DD + d4];
        float4 b2 = *(const float4*)&tbl[20 * DD + ((pa >> 16) & 255) * DD + d4];
        acc.x += fmaxf(hv.x + b0.x + b1.x + b2.x, 0.f);
        acc.y += fmaxf(hv.y + b0.y + b1.y + b2.y, 0.f);
        acc.z += fmaxf(hv.z + b0.z + b1.z + b2.z, 0.f);
        acc.w += fmaxf(hv.w + b0.w + b1.w + b2.w, 0.f);
    }
    float ope = 1.f + eps[l];
    float4 h0 = *(const float4*)&d_h[(size_t)node * DD + d4];
    float4 z;
    z.x = ope * h0.x + acc.x;
    z.y = ope * h0.y + acc.y;
    z.z = ope * h0.z + acc.z;
    z.w = ope * h0.w + acc.w;
    *(float4*)&d_zb[(size_t)node * DD + d4] = z;
}

// ================= fused GEMM + bias + BN (+relu) (+vn broadcast) =================
// out[M,Nout] = epilogue(A[M,K] @ W[K,Nout])
__device__ __forceinline__ void g_load(float (*Asb)[128], float (*Bsb)[128],
                                       const float* __restrict__ A, const float* __restrict__ W,
                                       int M, int K, int Nout,
                                       int row0, int col0, int kbase,
                                       int a_row, int a_c4, int b_row, int b_c4) {
    #pragma unroll
    for (int h2 = 0; h2 < 2; h2++) {
        int r = a_row + 64 * h2;
        int grow = row0 + r;
        float4 v = make_float4(0.f, 0.f, 0.f, 0.f);
        if (grow < M) v = *(const float4*)(A + (size_t)grow * K + kbase + a_c4 * 4);
        Asb[a_c4 * 4 + 0][r] = v.x;
        Asb[a_c4 * 4 + 1][r] = v.y;
        Asb[a_c4 * 4 + 2][r] = v.z;
        Asb[a_c4 * 4 + 3][r] = v.w;
    }
    #pragma unroll
    for (int h2 = 0; h2 < 2; h2++) {
        int r = b_row + 8 * h2;
        *(float4*)(&Bsb[r][b_c4 * 4]) =
            *(const float4*)(W + (size_t)(kbase + r) * Nout + col0 + b_c4 * 4);
    }
}

__global__ void __launch_bounds__(256) k_gemm(
    const float* __restrict__ A, const float* __restrict__ W,
    const float* __restrict__ bias,
    const float* __restrict__ p_g, const float* __restrict__ p_b,
    const float* __restrict__ p_m, const float* __restrict__ p_v,
    float* __restrict__ out,
    int M, int K, int Nout, int relu, int addvn,
    const int* __restrict__ batch, const float* __restrict__ vn) {
    __shared__ float As[2][16][128];
    __shared__ float Bs[2][16][128];
    const int tid = threadIdx.x;
    const int tx = tid & 15;
    const int ty = tid >> 4;
    const int row0 = blockIdx.y * 128;
    const int col0 = blockIdx.x * 128;

    // packed accumulators: acc2[i][jp] holds columns (2jp, 2jp+1) of the 8-wide j tile
    u64 acc2[8][4];
    #pragma unroll
    for (int i = 0; i < 8; i++)
        #pragma unroll
        for (int jp = 0; jp < 4; jp++) acc2[i][jp] = 0ull;   // bitpattern of (0.f,0.f)

    const int a_row = tid >> 2;
    const int a_c4  = tid & 3;
    const int b_row = tid >> 5;
    const int b_c4  = tid & 31;

    g_load(As[0], Bs[0], A, W, M, K, Nout, row0, col0, 0, a_row, a_c4, b_row, b_c4);
    __syncthreads();

    int nk = K >> 4;
    int buf = 0;
    for (int t = 0; t < nk; ++t) {
        if (t + 1 < nk)
            g_load(As[buf ^ 1], Bs[buf ^ 1], A, W, M, K, Nout, row0, col0,
                   (t + 1) * 16, a_row, a_c4, b_row, b_c4);
        #pragma unroll
        for (int k = 0; k < 16; k++) {
            float a[8], b[8];
            *(float4*)&a[0] = *(const float4*)&As[buf][k][ty * 4];
            *(float4*)&a[4] = *(const float4*)&As[buf][k][64 + ty * 4];
            *(float4*)&b[0] = *(const float4*)&Bs[buf][k][tx * 4];
            *(float4*)&b[4] = *(const float4*)&Bs[buf][k][64 + tx * 4];
            u64 bp[4];
            #pragma unroll
            for (int jp = 0; jp < 4; jp++) bp[jp] = pack2(b[2 * jp], b[2 * jp + 1]);
            #pragma unroll
            for (int i = 0; i < 8; i++) {
                u64 ad = dup2(a[i]);
                #pragma unroll
                for (int jp = 0; jp < 4; jp++) ffma2(acc2[i][jp], ad, bp[jp]);
            }
        }
        __syncthreads();
        buf ^= 1;
    }

    // epilogue: y = (acc + bias - m) * g*rsqrt(v+eps) + b ; [relu] ; [+= vn[batch]]
    float sc[8], co[8];
    #pragma unroll
    for (int j = 0; j < 8; j++) {
        int c = col0 + ((j < 4) ? tx * 4 + j : 64 + tx * 4 + (j - 4));
        float s = p_g[c] * rsqrtf(p_v[c] + 1e-5f);
        sc[j] = s;
        co[j] = bias[c] * s + (p_b[c] - p_m[c] * s);
    }
    #pragma unroll
    for (int i = 0; i < 8; i++) {
        int r = row0 + ((i < 4) ? ty * 4 + i : 64 + ty * 4 + (i - 4));
        if (r >= M) continue;
        float vadd[8];
        if (addvn) {   // only used when Nout==128, col0==0
            const float* vr = vn + (size_t)batch[r] * DD;
            *(float4*)&vadd[0] = *(const float4*)(vr + tx * 4);
            *(float4*)&vadd[4] = *(const float4*)(vr + 64 + tx * 4);
        }
        float acc[8];
        #pragma unroll
        for (int jp = 0; jp < 4; jp++) {
            float2 u = unpack2(acc2[i][jp]);
            acc[2 * jp] = u.x; acc[2 * jp + 1] = u.y;
        }
        float y[8];
        #pragma unroll
        for (int j = 0; j < 8; j++) {
            float yy = acc[j] * sc[j] + co[j];
            if (relu) yy = fmaxf(yy, 0.f);
            if (addvn) yy += vadd[j];
            y[j] = yy;
        }
        float* orow = out + (size_t)r * Nout + col0;
        *(float4*)(orow + tx * 4)      = make_float4(y[0], y[1], y[2], y[3]);
        *(float4*)(orow + 64 + tx * 4) = make_float4(y[4], y[5], y[6], y[7]);
    }
}

// ================= launch =================
extern "C" void kernel_launch(void* const* d_in, const int* in_sizes, int n_in,
                              void* d_out, int out_size) {
    const int*   x_atom     = (const int*)d_in[0];
    const int*   edge_index = (const int*)d_in[1];
    const int*   edge_attr  = (const int*)d_in[2];
    const int*   batch      = (const int*)d_in[3];
    const float* atom_emb   = (const float*)d_in[4];
    const float* vn0        = (const float*)d_in[5];
    const float* bond_emb   = (const float*)d_in[6];
    const float* eps        = (const float*)d_in[7];
    const float* mlp_W1     = (const float*)d_in[8];
    const float* mlp_b1     = (const float*)d_in[9];
    const float* mlp_bn1_g  = (const float*)d_in[10];
    const float* mlp_bn1_b  = (const float*)d_in[11];
    const float* mlp_bn1_m  = (const float*)d_in[12];
    const float* mlp_bn1_v  = (const float*)d_in[13];
    const float* mlp_W2     = (const float*)d_in[14];
    const float* mlp_b2     = (const float*)d_in[15];
    const float* bn_g       = (const float*)d_in[16];
    const float* bn_b       = (const float*)d_in[17];
    const float* bn_m       = (const float*)d_in[18];
    const float* bn_v       = (const float*)d_in[19];
    const float* vn_W1      = (const float*)d_in[20];
    const float* vn_b1      = (const float*)d_in[21];
    const float* vn_bn1_g   = (const float*)d_in[22];
    const float* vn_bn1_b   = (const float*)d_in[23];
    const float* vn_bn1_m   = (const float*)d_in[24];
    const float* vn_bn1_v   = (const float*)d_in[25];
    const float* vn_W2      = (const float*)d_in[26];
    const float* vn_b2      = (const float*)d_in[27];
    const float* vn_bn2_g   = (const float*)d_in[28];
    const float* vn_bn2_b   = (const float*)d_in[29];
    const float* vn_bn2_m   = (const float*)d_in[30];
    const float* vn_bn2_v   = (const float*)d_in[31];

    float *p_h, *p_z, *p_t, *p_vn, *p_vnagg, *p_vnt;
    cudaGetSymbolAddress((void**)&p_h,     d_h);
    cudaGetSymbolAddress((void**)&p_z,     d_zb);
    cudaGetSymbolAddress((void**)&p_t,     d_tb);
    cudaGetSymbolAddress((void**)&p_vn,    d_vn);
    cudaGetSymbolAddress((void**)&p_vnagg, d_vnagg);
    cudaGetSymbolAddress((void**)&p_vnt,   d_vnt);

    // CSR build (edge structure is layer-invariant)
    k_zero_deg<<<(NN + 255) / 256, 256>>>();
    k_hist<<<(NE + 255) / 256, 256>>>(edge_index);
    k_scan<<<1, 1024>>>();
    k_scatter<<<(NE + 255) / 256, 256>>>(edge_index, edge_attr);

    // encoders
    k_atom<<<NN, 128>>>(x_atom, atom_emb, vn0);
    k_vninit<<<NG, 128>>>(vn0);

    const int gM  = (NN + 127) / 128;   // 391
    const int gMg = (NG + 127) / 128;   // 8

    for (int l = 0; l < NL; ++l) {
        // z = (1+eps)h + sum relu(h[src]+e)
        k_aggregate<<<(NN + 7) / 8, 256>>>(bond_emb + (size_t)l * 3 * 10 * DD, eps, l);

        if (l < NL - 1) {
            // virtual node update (uses pre-conv h)
            k_vnagg<<<NG, 256>>>(batch);
            k_gemm<<<dim3(2, gMg), 256>>>(p_vnagg, vn_W1 + (size_t)l * 128 * 256,
                                          vn_b1 + l * 256,
                                          vn_bn1_g + l * 256, vn_bn1_b + l * 256,
                                          vn_bn1_m + l * 256, vn_bn1_v + l * 256,
                                          p_vnt, NG, 128, 256, 1, 0, nullptr, nullptr);
            k_gemm<<<dim3(1, gMg), 256>>>(p_vnt, vn_W2 + (size_t)l * 256 * 128,
                                          vn_b2 + l * 128,
                                          vn_bn2_g + l * 128, vn_bn2_b + l * 128,
                                          vn_bn2_m + l * 128, vn_bn2_v + l * 128,
                                          p_vn, NG, 256, 128, 1, 0, nullptr, nullptr);
        }

        // node MLP
        k_gemm<<<dim3(2, gM), 256>>>(p_z, mlp_W1 + (size_t)l * 128 * 256,
                                     mlp_b1 + l * 256,
                                     mlp_bn1_g + l * 256, mlp_bn1_b + l * 256,
                                     mlp_bn1_m + l * 256, mlp_bn1_v + l * 256,
                                     p_t, NN, 128, 256, 1, 0, nullptr, nullptr);
        int last = (l == NL - 1);
        float* outp = last ? (float*)d_out : p_h;
        // for l<L-1: relu, then fuse next layer's h += vn[batch] into epilogue
        k_gemm<<<dim3(1, gM), 256>>>(p_t, mlp_W2 + (size_t)l * 256 * 128,
                                     mlp_b2 + l * 128,
                                     bn_g + l * 128, bn_b + l * 128,
                                     bn_m + l * 128, bn_v + l * 128,
                                     outp, NN, 256, 128, last ? 0 : 1, last ? 0 : 1,
                                     batch, p_vn);
    }
}

// round 4
// speedup vs baseline: 1.3870x; 1.3870x over previous
#include <cuda_runtime.h>
#include <cstdint>
#include <math.h>

#define NN 50000
#define NE 800000
#define NG 1024
#define DD 128
#define NL 3

// ===================== scratch (device globals) =====================
__device__ float d_h[(size_t)NN * DD];
__device__ float d_zb[(size_t)NN * DD];
__device__ float d_tb[(size_t)NN * 2 * DD];
__device__ float d_vn[NG * DD];
__device__ float d_vnagg[NG * DD];
__device__ float d_vnt[NG * 2 * DD];
__device__ int   d_deg[NN];
__device__ int   d_off[NN];
__device__ int   d_cur[NN];
__device__ int   d_srcs[NE];
__device__ int   d_attrs[NE];
// transposed weights (B operand is [Nout,K], K contiguous)
__device__ float d_wt1[NL * 256 * 128];
__device__ float d_wt2[NL * 128 * 256];
__device__ float d_wtv1[(NL - 1) * 256 * 128];
__device__ float d_wtv2[(NL - 1) * 128 * 256];

__device__ __forceinline__ uint32_t to_tf32(float f) {
    uint32_t r; asm("cvt.rna.tf32.f32 %0, %1;" : "=r"(r) : "f"(f)); return r;
}
__device__ __forceinline__ float to_tf32f(float f) {
    return __uint_as_float(to_tf32(f));
}
__device__ __forceinline__ void mma_tf32(float* d, const uint32_t* a, const uint32_t* b) {
    asm volatile(
        "mma.sync.aligned.m16n8k8.row.col.f32.tf32.tf32.f32 "
        "{%0,%1,%2,%3}, {%4,%5,%6,%7}, {%8,%9}, {%0,%1,%2,%3};"
        : "+f"(d[0]), "+f"(d[1]), "+f"(d[2]), "+f"(d[3])
        : "r"(a[0]), "r"(a[1]), "r"(a[2]), "r"(a[3]), "r"(b[0]), "r"(b[1]));
}

// ===================== CSR build =====================
__global__ void k_zero_deg() {
    int i = blockIdx.x * blockDim.x + threadIdx.x;
    if (i < NN) d_deg[i] = 0;
}
__global__ void k_hist(const int* __restrict__ ei) {
    int e = blockIdx.x * blockDim.x + threadIdx.x;
    if (e < NE) atomicAdd(&d_deg[ei[NE + e]], 1);
}
// segmented exclusive scan (1024 threads, contiguous chunks)
__global__ void k_scan() {
    __shared__ int wsum[32];
    const int C = (NN + 1023) / 1024;
    int tid = threadIdx.x, lane = tid & 31, w = tid >> 5;
    int base = tid * C;
    int s = 0;
    for (int i = 0; i < C; i++) { int idx = base + i; if (idx < NN) s += d_deg[idx]; }
    int x = s;
    #pragma unroll
    for (int o = 1; o < 32; o <<= 1) {
        int y = __shfl_up_sync(0xffffffffu, x, o);
        if (lane >= o) x += y;
    }
    if (lane == 31) wsum[w] = x;
    __syncthreads();
    if (w == 0) {
        int v = wsum[lane];
        #pragma unroll
        for (int o = 1; o < 32; o <<= 1) {
            int y = __shfl_up_sync(0xffffffffu, v, o);
            if (lane >= o) v += y;
        }
        wsum[lane] = v;
    }
    __syncthreads();
    int run = ((w > 0) ? wsum[w - 1] : 0) + (x - s);
    for (int i = 0; i < C; i++) {
        int idx = base + i;
        if (idx < NN) { d_off[idx] = run; d_cur[idx] = run; run += d_deg[idx]; }
    }
}
__global__ void k_scatter(const int* __restrict__ ei, const int* __restrict__ ea) {
    int e = blockIdx.x * blockDim.x + threadIdx.x;
    if (e >= NE) return;
    int dst = ei[NE + e];
    int pos = atomicAdd(&d_cur[dst], 1);
    d_srcs[pos]  = ei[e];
    d_attrs[pos] = ea[3 * e] | (ea[3 * e + 1] << 8) | (ea[3 * e + 2] << 16);
}

// ===================== weight transpose =====================
__global__ void k_transpose(const float* __restrict__ in, float* __restrict__ out,
                            int R, int C) {
    __shared__ float t[32][33];
    size_t lofs = (size_t)blockIdx.z * R * C;
    in += lofs; out += lofs;
    int c0 = blockIdx.x * 32, r0 = blockIdx.y * 32;
    for (int i = threadIdx.y; i < 32; i += 8)
        t[i][threadIdx.x] = in[(size_t)(r0 + i) * C + c0 + threadIdx.x];
    __syncthreads();
    for (int i = threadIdx.y; i < 32; i += 8)
        out[(size_t)(c0 + i) * R + r0 + threadIdx.x] = t[threadIdx.x][i];
}

// ===================== encoders / vn =====================
__global__ void k_atom(const int* __restrict__ x_atom,
                       const float* __restrict__ atom_emb,
                       const float* __restrict__ vn0) {
    int n = blockIdx.x;
    int d = threadIdx.x;
    const int* xr = x_atom + n * 9;
    float s = vn0[d];
    #pragma unroll
    for (int f = 0; f < 9; f++)
        s += atom_emb[(f * 100 + xr[f]) * DD + d];
    d_h[(size_t)n * DD + d] = s;
}
__global__ void k_vninit(const float* __restrict__ vn0) {
    d_vn[blockIdx.x * DD + threadIdx.x] = vn0[threadIdx.x];
}
__global__ void k_vnagg(const int* __restrict__ batch) {
    __shared__ int s_se[2];
    __shared__ float s_acc[DD];
    int g = blockIdx.x;
    if (threadIdx.x < 2) {
        int target = g + threadIdx.x;
        int lo = 0, hi = NN;
        while (lo < hi) {
            int mid = (lo + hi) >> 1;
            if (batch[mid] < target) lo = mid + 1; else hi = mid;
        }
        s_se[threadIdx.x] = lo;
    }
    __syncthreads();
    int start = s_se[0], end = s_se[1];
    int d = threadIdx.x & (DD - 1);
    int half = threadIdx.x >> 7;
    float acc = 0.f;
    for (int n = start + half; n < end; n += 2)
        acc += d_h[(size_t)n * DD + d];
    if (half == 0) s_acc[d] = acc;
    __syncthreads();
    if (half == 1)
        d_vnagg[g * DD + d] = (acc + s_acc[d]) + d_vn[g * DD + d];
}

// ===================== CSR-gather aggregation =====================
__global__ void __launch_bounds__(256) k_aggregate(const float* __restrict__ bond_l,
                                                   const float* __restrict__ eps, int l) {
    __shared__ float tbl[3 * 10 * DD];
    for (int i = threadIdx.x; i < 3 * 10 * DD; i += 256) tbl[i] = bond_l[i];
    __syncthreads();
    int node = blockIdx.x * 8 + (threadIdx.x >> 5);
    if (node >= NN) return;
    int lane = threadIdx.x & 31;
    int d4 = lane * 4;
    int start = d_off[node];
    int deg   = d_deg[node];
    float4 acc = make_float4(0.f, 0.f, 0.f, 0.f);
    int j = 0;
    for (; j + 2 <= deg; j += 2) {
        int s0 = d_srcs[start + j],     p0 = d_attrs[start + j];
        int s1 = d_srcs[start + j + 1], p1 = d_attrs[start + j + 1];
        float4 hv0 = *(const float4*)&d_h[(size_t)s0 * DD + d4];
        float4 hv1 = *(const float4*)&d_h[(size_t)s1 * DD + d4];
        float4 a0 = *(const float4*)&tbl[(p0 & 255) * DD + d4];
        float4 a1 = *(const float4*)&tbl[10 * DD + ((p0 >> 8) & 255) * DD + d4];
        float4 a2 = *(const float4*)&tbl[20 * DD + ((p0 >> 16) & 255) * DD + d4];
        float4 c0 = *(const float4*)&tbl[(p1 & 255) * DD + d4];
        float4 c1 = *(const float4*)&tbl[10 * DD + ((p1 >> 8) & 255) * DD + d4];
        float4 c2 = *(const float4*)&tbl[20 * DD + ((p1 >> 16) & 255) * DD + d4];
        acc.x += fmaxf(hv0.x + a0.x + a1.x + a2.x, 0.f) + fmaxf(hv1.x + c0.x + c1.x + c2.x, 0.f);
        acc.y += fmaxf(hv0.y + a0.y + a1.y + a2.y, 0.f) + fmaxf(hv1.y + c0.y + c1.y + c2.y, 0.f);
        acc.z += fmaxf(hv0.z + a0.z + a1.z + a2.z, 0.f) + fmaxf(hv1.z + c0.z + c1.z + c2.z, 0.f);
        acc.w += fmaxf(hv0.w + a0.w + a1.w + a2.w, 0.f) + fmaxf(hv1.w + c0.w + c1.w + c2.w, 0.f);
    }
    if (j < deg) {
        int src = d_srcs[start + j];
        int pa  = d_attrs[start + j];
        float4 hv = *(const float4*)&d_h[(size_t)src * DD + d4];
        float4 b0 = *(const float4*)&tbl[(pa & 255) * DD + d4];
        float4 b1 = *(const float4*)&tbl[10 * DD + ((pa >> 8) & 255) * DD + d4];
        float4 b2 = *(const float4*)&tbl[20 * DD + ((pa >> 16) & 255) * DD + d4];
        acc.x += fmaxf(hv.x + b0.x + b1.x + b2.x, 0.f);
        acc.y += fmaxf(hv.y + b0.y + b1.y + b2.y, 0.f);
        acc.z += fmaxf(hv.z + b0.z + b1.z + b2.z, 0.f);
        acc.w += fmaxf(hv.w + b0.w + b1.w + b2.w, 0.f);
    }
    float ope = 1.f + eps[l];
    float4 h0 = *(const float4*)&d_h[(size_t)node * DD + d4];
    float4 z;
    z.x = ope * h0.x + acc.x;
    z.y = ope * h0.y + acc.y;
    z.z = ope * h0.z + acc.z;
    z.w = ope * h0.w + acc.w;
    *(float4*)&d_zb[(size_t)node * DD + d4] = z;
}

// ===================== tf32 mma.sync GEMM + fused BN epilogue =====================
// out[M,Nout] = epi(A[M,K] @ WT[Nout,K]^T). CTA tile 128x128, warp tile 64x32,
// k16 chunks double-buffered, fragment-scattered smem (tf32 cvt at staging).
// smem: aS[2][2048]f + bS[2][2048]f = 32KB, + sc/co 1KB.
__global__ void __launch_bounds__(256) k_gemm_mma(
    const float* __restrict__ A, const float* __restrict__ WT,
    const float* __restrict__ bias,
    const float* __restrict__ pg, const float* __restrict__ pb,
    const float* __restrict__ pm, const float* __restrict__ pv,
    float* __restrict__ out, int M, int K, int Nout,
    int relu, int addvn, const int* __restrict__ batch, const float* __restrict__ vn) {
    __shared__ float aS[2][2048];
    __shared__ float bS[2][2048];
    __shared__ float scs[128], cos_[128];

    const int tid  = threadIdx.x;
    const int lane = tid & 31;
    const int wid  = tid >> 5;
    const int wm   = wid >> 2;        // 0..1 (64 rows each)
    const int wn   = wid & 3;         // 0..3 (32 cols each)
    const int row0 = blockIdx.x * 128;
    const int col0 = blockIdx.y * 128;

    float acc[4][4][4];
    #pragma unroll
    for (int mt = 0; mt < 4; mt++)
        #pragma unroll
        for (int nt = 0; nt < 4; nt++)
            #pragma unroll
            for (int q = 0; q < 4; q++) acc[mt][nt][q] = 0.f;

    const int nc = K >> 4;            // k16 chunks
    float4 pa[2], pb2[2];

    // ---- prologue: load + stage chunk 0
    #pragma unroll
    for (int i = 0; i < 2; i++) {
        int idx = tid + i * 256;
        int r = idx >> 2, c4 = idx & 3;
        int gr = row0 + r;
        pa[i] = (gr < M) ? *(const float4*)(A + (size_t)gr * K + c4 * 4)
                         : make_float4(0.f, 0.f, 0.f, 0.f);
        pb2[i] = *(const float4*)(WT + (size_t)(col0 + r) * K + c4 * 4);
    }
    #pragma unroll
    for (int i = 0; i < 2; i++) {
        int idx = tid + i * 256;
        int r = idx >> 2, c4 = idx & 3;
        float av[4] = {pa[i].x, pa[i].y, pa[i].z, pa[i].w};
        float bv[4] = {pb2[i].x, pb2[i].y, pb2[i].z, pb2[i].w};
        #pragma unroll
        for (int j = 0; j < 4; j++) {
            int c = c4 * 4 + j;
            int s = c >> 3, kk = c & 7;
            // A: (r, c) -> aS[s][r>>4][lane][reg]
            aS[0][(s * 8 + (r >> 4)) * 128 + ((r & 7) * 4 + (kk & 3)) * 4 +
                  ((r >> 3) & 1) + 2 * (kk >> 2)] = to_tf32f(av[j]);
            // B: (n=r, k=c) -> bS[s][r>>3][lane][reg]
            bS[0][(s * 16 + (r >> 3)) * 64 + ((r & 7) * 4 + (kk & 3)) * 2 +
                  (kk >> 2)] = to_tf32f(bv[j]);
        }
    }

    for (int t = 0; t < nc; ++t) {
        __syncthreads();
        int buf = t & 1;
        int kb1 = (t + 1) * 16;
        if (t + 1 < nc) {
            #pragma unroll
            for (int i = 0; i < 2; i++) {
                int idx = tid + i * 256;
                int r = idx >> 2, c4 = idx & 3;
                int gr = row0 + r;
                pa[i] = (gr < M) ? *(const float4*)(A + (size_t)gr * K + kb1 + c4 * 4)
                                 : make_float4(0.f, 0.f, 0.f, 0.f);
                pb2[i] = *(const float4*)(WT + (size_t)(col0 + r) * K + kb1 + c4 * 4);
            }
        }
        // ---- compute this chunk (2 k8 steps)
        #pragma unroll
        for (int s = 0; s < 2; s++) {
            uint32_t af[4][4], bf[4][2];
            #pragma unroll
            for (int mt = 0; mt < 4; mt++)
                *(float4*)af[mt] = *(const float4*)&aS[buf][(s * 8 + wm * 4 + mt) * 128 + lane * 4];
            #pragma unroll
            for (int nt = 0; nt < 4; nt++)
                *(float2*)bf[nt] = *(const float2*)&bS[buf][(s * 16 + wn * 4 + nt) * 64 + lane * 2];
            #pragma unroll
            for (int mt = 0; mt < 4; mt++)
                #pragma unroll
                for (int nt = 0; nt < 4; nt++)
                    mma_tf32(acc[mt][nt], af[mt], bf[nt]);
        }
        // ---- stage next chunk into other buffer
        if (t + 1 < nc) {
            int nb = buf ^ 1;
            #pragma unroll
            for (int i = 0; i < 2; i++) {
                int idx = tid + i * 256;
                int r = idx >> 2, c4 = idx & 3;
                float av[4] = {pa[i].x, pa[i].y, pa[i].z, pa[i].w};
                float bv[4] = {pb2[i].x, pb2[i].y, pb2[i].z, pb2[i].w};
                #pragma unroll
                for (int j = 0; j < 4; j++) {
                    int c = c4 * 4 + j;
                    int s = c >> 3, kk = c & 7;
                    aS[nb][(s * 8 + (r >> 4)) * 128 + ((r & 7) * 4 + (kk & 3)) * 4 +
                           ((r >> 3) & 1) + 2 * (kk >> 2)] = to_tf32f(av[j]);
                    bS[nb][(s * 16 + (r >> 3)) * 64 + ((r & 7) * 4 + (kk & 3)) * 2 +
                           (kk >> 2)] = to_tf32f(bv[j]);
                }
            }
        }
    }

    // BN fold tables for this 128-col block
    if (tid < 128) {
        int c = col0 + tid;
        float s = pg[c] * rsqrtf(pv[c] + 1e-5f);
        scs[tid] = s;
        cos_[tid] = bias[c] * s + (pb[c] - pm[c] * s);
    }
    __syncthreads();

    // epilogue
    const int g   = lane >> 2;
    const int tig = lane & 3;
    #pragma unroll
    for (int mt = 0; mt < 4; mt++) {
        #pragma unroll
        for (int half = 0; half < 2; half++) {
            int r = row0 + wm * 64 + mt * 16 + g + half * 8;
            if (r >= M) continue;
            const float* vr = addvn ? (vn + (size_t)batch[r] * DD) : nullptr;
            #pragma unroll
            for (int nt = 0; nt < 4; nt++) {
                int lc = wn * 32 + nt * 8 + 2 * tig;     // local col in [0,128)
                float y0 = acc[mt][nt][half * 2 + 0] * scs[lc] + cos_[lc];
                float y1 = acc[mt][nt][half * 2 + 1] * scs[lc + 1] + cos_[lc + 1];
                if (relu) { y0 = fmaxf(y0, 0.f); y1 = fmaxf(y1, 0.f); }
                if (vr)   { y0 += vr[lc]; y1 += vr[lc + 1]; }
                *(float2*)(out + (size_t)r * Nout + col0 + lc) = make_float2(y0, y1);
            }
        }
    }
}

// ===================== launch =====================
extern "C" void kernel_launch(void* const* d_in, const int* in_sizes, int n_in,
                              void* d_out, int out_size) {
    const int*   x_atom     = (const int*)d_in[0];
    const int*   edge_index = (const int*)d_in[1];
    const int*   edge_attr  = (const int*)d_in[2];
    const int*   batch      = (const int*)d_in[3];
    const float* atom_emb   = (const float*)d_in[4];
    const float* vn0        = (const float*)d_in[5];
    const float* bond_emb   = (const float*)d_in[6];
    const float* eps        = (const float*)d_in[7];
    const float* mlp_W1     = (const float*)d_in[8];
    const float* mlp_b1     = (const float*)d_in[9];
    const float* mlp_bn1_g  = (const float*)d_in[10];
    const float* mlp_bn1_b  = (const float*)d_in[11];
    const float* mlp_bn1_m  = (const float*)d_in[12];
    const float* mlp_bn1_v  = (const float*)d_in[13];
    const float* mlp_W2     = (const float*)d_in[14];
    const float* mlp_b2     = (const float*)d_in[15];
    const float* bn_g       = (const float*)d_in[16];
    const float* bn_b       = (const float*)d_in[17];
    const float* bn_m       = (const float*)d_in[18];
    const float* bn_v       = (const float*)d_in[19];
    const float* vn_W1      = (const float*)d_in[20];
    const float* vn_b1      = (const float*)d_in[21];
    const float* vn_bn1_g   = (const float*)d_in[22];
    const float* vn_bn1_b   = (const float*)d_in[23];
    const float* vn_bn1_m   = (const float*)d_in[24];
    const float* vn_bn1_v   = (const float*)d_in[25];
    const float* vn_W2      = (const float*)d_in[26];
    const float* vn_b2      = (const float*)d_in[27];
    const float* vn_bn2_g   = (const float*)d_in[28];
    const float* vn_bn2_b   = (const float*)d_in[29];
    const float* vn_bn2_m   = (const float*)d_in[30];
    const float* vn_bn2_v   = (const float*)d_in[31];

    float *p_h, *p_z, *p_t, *p_vn, *p_vnagg, *p_vnt;
    float *p_wt1, *p_wt2, *p_wtv1, *p_wtv2;
    cudaGetSymbolAddress((void**)&p_h,     d_h);
    cudaGetSymbolAddress((void**)&p_z,     d_zb);
    cudaGetSymbolAddress((void**)&p_t,     d_tb);
    cudaGetSymbolAddress((void**)&p_vn,    d_vn);
    cudaGetSymbolAddress((void**)&p_vnagg, d_vnagg);
    cudaGetSymbolAddress((void**)&p_vnt,   d_vnt);
    cudaGetSymbolAddress((void**)&p_wt1,   d_wt1);
    cudaGetSymbolAddress((void**)&p_wt2,   d_wt2);
    cudaGetSymbolAddress((void**)&p_wtv1,  d_wtv1);
    cudaGetSymbolAddress((void**)&p_wtv2,  d_wtv2);

    dim3 tb(32, 8);
    k_transpose<<<dim3(256 / 32, 128 / 32, NL),     tb>>>(mlp_W1, p_wt1, 128, 256);
    k_transpose<<<dim3(128 / 32, 256 / 32, NL),     tb>>>(mlp_W2, p_wt2, 256, 128);
    k_transpose<<<dim3(256 / 32, 128 / 32, NL - 1), tb>>>(vn_W1,  p_wtv1, 128, 256);
    k_transpose<<<dim3(128 / 32, 256 / 32, NL - 1), tb>>>(vn_W2,  p_wtv2, 256, 128);

    k_zero_deg<<<(NN + 255) / 256, 256>>>();
    k_hist<<<(NE + 255) / 256, 256>>>(edge_index);
    k_scan<<<1, 1024>>>();
    k_scatter<<<(NE + 255) / 256, 256>>>(edge_index, edge_attr);

    k_atom<<<NN, 128>>>(x_atom, atom_emb, vn0);
    k_vninit<<<NG, 128>>>(vn0);

    const int gM  = (NN + 127) / 128;   // 391
    const int gMg = NG / 128;           // 8

    for (int l = 0; l < NL; ++l) {
        k_aggregate<<<(NN + 7) / 8, 256>>>(bond_emb + (size_t)l * 3 * 10 * DD, eps, l);

        if (l < NL - 1) {
            k_vnagg<<<NG, 256>>>(batch);
            k_gemm_mma<<<dim3(gMg, 2), 256>>>(
                p_vnagg, p_wtv1 + (size_t)l * 256 * 128, vn_b1 + l * 256,
                vn_bn1_g + l * 256, vn_bn1_b + l * 256, vn_bn1_m + l * 256, vn_bn1_v + l * 256,
                p_vnt, NG, 128, 256, 1, 0, nullptr, nullptr);
            k_gemm_mma<<<dim3(gMg, 1), 256>>>(
                p_vnt, p_wtv2 + (size_t)l * 128 * 256, vn_b2 + l * 128,
                vn_bn2_g + l * 128, vn_bn2_b + l * 128, vn_bn2_m + l * 128, vn_bn2_v + l * 128,
                p_vn, NG, 256, 128, 1, 0, nullptr, nullptr);
        }

        k_gemm_mma<<<dim3(gM, 2), 256>>>(
            p_z, p_wt1 + (size_t)l * 256 * 128, mlp_b1 + l * 256,
            mlp_bn1_g + l * 256, mlp_bn1_b + l * 256, mlp_bn1_m + l * 256, mlp_bn1_v + l * 256,
            p_t, NN, 128, 256, 1, 0, nullptr, nullptr);
        int last = (l == NL - 1);
        float* outp = last ? (float*)d_out : p_h;
        k_gemm_mma<<<dim3(gM, 1), 256>>>(
            p_t, p_wt2 + (size_t)l * 128 * 256, mlp_b2 + l * 128,
            bn_g + l * 128, bn_b + l * 128, bn_m + l * 128, bn_v + l * 128,
            outp, NN, 256, 128, last ? 0 : 1, last ? 0 : 1, batch, p_vn);
    }
}